// round 1
// baseline (speedup 1.0000x reference)
#include <cuda_runtime.h>
#include <cuda_bf16.h>

#define BATCH 8
#define SEQ   512
#define DIM   512
#define TSTEP 16
#define DECAY 0.9f
#define THRESH 1.0f

// One thread handles 4 consecutive embedding dims for one (b, s).
// Loads float4 from the gathered table row, computes sigmoid rates,
// runs the 16-step LIF in registers, streams 16 float4 spikes to out.
__global__ __launch_bounds__(256) void spiking_embed_kernel(
    const int*   __restrict__ ids,     // [BATCH, SEQ]
    const float* __restrict__ table,   // [VOCAB, DIM]
    float*       __restrict__ out)     // [BATCH, TSTEP, SEQ, DIM]
{
    const int D4 = DIM / 4;                       // 128
    int idx = blockIdx.x * blockDim.x + threadIdx.x;   // over BATCH*SEQ*D4
    int d4 = idx % D4;
    int s  = (idx / D4) % SEQ;
    int b  = idx / (D4 * SEQ);

    int token = ids[b * SEQ + s];
    const float4 e = *reinterpret_cast<const float4*>(
        table + (size_t)token * DIM + d4 * 4);

    // fp32 sigmoid (matches JAX fp32)
    float4 r;
    r.x = 1.0f / (1.0f + expf(-e.x));
    r.y = 1.0f / (1.0f + expf(-e.y));
    r.z = 1.0f / (1.0f + expf(-e.z));
    r.w = 1.0f / (1.0f + expf(-e.w));

    float vx = 0.f, vy = 0.f, vz = 0.f, vw = 0.f;

    // out offset for t=0: ((b*T + t)*SEQ + s)*DIM + d
    size_t base = (((size_t)b * TSTEP) * SEQ + s) * (size_t)DIM + (size_t)d4 * 4;
    float4* outp = reinterpret_cast<float4*>(out + base);
    const size_t tstride4 = (size_t)SEQ * DIM / 4;   // float4 stride per timestep

    #pragma unroll
    for (int t = 0; t < TSTEP; t++) {
        vx = DECAY * vx + r.x;
        vy = DECAY * vy + r.y;
        vz = DECAY * vz + r.z;
        vw = DECAY * vw + r.w;
        float4 sp;
        sp.x = (vx >= THRESH) ? 1.0f : 0.0f;
        sp.y = (vy >= THRESH) ? 1.0f : 0.0f;
        sp.z = (vz >= THRESH) ? 1.0f : 0.0f;
        sp.w = (vw >= THRESH) ? 1.0f : 0.0f;
        vx -= sp.x * THRESH;
        vy -= sp.y * THRESH;
        vz -= sp.z * THRESH;
        vw -= sp.w * THRESH;
        __stcs(outp + (size_t)t * tstride4, sp);   // streaming store, write-once data
    }
}

extern "C" void kernel_launch(void* const* d_in, const int* in_sizes, int n_in,
                              void* d_out, int out_size) {
    // Identify inputs by size: ids has BATCH*SEQ elems, table is much larger.
    const int*   ids;
    const float* table;
    if (in_sizes[0] == BATCH * SEQ) {
        ids   = (const int*)d_in[0];
        table = (const float*)d_in[1];
    } else {
        ids   = (const int*)d_in[1];
        table = (const float*)d_in[0];
    }
    float* out = (float*)d_out;

    const int total = BATCH * SEQ * (DIM / 4);   // 524288 threads
    const int threads = 256;
    const int blocks = (total + threads - 1) / threads;
    spiking_embed_kernel<<<blocks, threads>>>(ids, table, out);
}